// round 1
// baseline (speedup 1.0000x reference)
#include <cuda_runtime.h>
#include <math.h>

#define VOLD   256
#define WW     32
#define NGAUSS 4000

// ---------------------------------------------------------------------------
// Kernel 1: zero the volume (d_out is poisoned to 0xAA by the harness).
// ---------------------------------------------------------------------------
__global__ void zero_kernel(float4* __restrict__ out, int n4) {
    int i = blockIdx.x * blockDim.x + threadIdx.x;
    int stride = gridDim.x * blockDim.x;
    float4 z = make_float4(0.f, 0.f, 0.f, 0.f);
    for (; i < n4; i += stride) out[i] = z;
}

// ---------------------------------------------------------------------------
// Kernel 2: one block per Gaussian. Separable weights in shared memory, then
// vectorized global reductions (red.global.add.v4.f32) along z.
// ---------------------------------------------------------------------------
__global__ __launch_bounds__(256) void splat_kernel(
    const float* __restrict__ centers,     // (N,3) normalized [0,1]
    const float* __restrict__ sigmas,      // (N,)
    const float* __restrict__ intens,      // (N,)
    float* __restrict__ vol)               // (256,256,256)
{
    const int g = blockIdx.x;
    const int t = threadIdx.x;

    __shared__ float swx[WW];                      // intensity folded in
    __shared__ float swy[WW];
    __shared__ __align__(16) float swz[36];        // 4-aligned z footprint
    __shared__ int s_start[3];                     // start_x, start_y, z_aligned

    const float sig    = sigmas[g];
    const float inv2s2 = 0.5f / (sig * sig);
    const float I      = intens[g];
    const float cut    = 3.0f * sig * 255.0f;      // cutoff in voxel units

    // ---- Phase 1: per-axis weights (threads 0..99) ----
    if (t < 100) {
        int axis, o;
        if (t < 32)      { axis = 0; o = t; }
        else if (t < 64) { axis = 1; o = t - 32; }
        else             { axis = 2; o = t - 64; }   // 36 z lanes

        const float cn = centers[3 * g + axis];      // normalized center
        const float cv = cn * 255.0f;                // voxel-space center

        const float minf = fmaxf(cv - cut, 0.0f);
        const float maxf = fminf(cv + cut, 255.0f);
        const int   mini = (int)floorf(minf);                       // >= 0
        const int   maxi = min((int)floorf(maxf) + 1, VOLD);        // exclusive
        const int   start = min(mini, VOLD - WW);                   // clip to 224

        int idx;
        if (axis < 2) {
            idx = start + o;
        } else {
            idx = (start & ~3) + o;                  // aligned z footprint
        }

        // Window containment is implied by the bbox check (extent <= 29 < 32):
        float w = 0.0f;
        if (idx >= mini && idx < maxi) {
            const float d = (float)idx * (1.0f / 255.0f) - cn;
            w = expf(-d * d * inv2s2);
        }

        if (axis == 0)      swx[o] = w * I;
        else if (axis == 1) swy[o] = w;
        else                swz[o] = w;

        if (o == 0) s_start[axis] = (axis < 2) ? start : (start & ~3);
    }
    __syncthreads();

    // ---- Phase 2: scatter. 1024 (x,y) rows over 256 threads, 4 rows each ----
    const int sx  = s_start[0];
    const int sy  = s_start[1];
    const int zal = s_start[2];

    // z-weights into registers (reused across the thread's 4 rows)
    float wz[36];
#pragma unroll
    for (int i = 0; i < 36; ++i) wz[i] = swz[i];

    // Per-quad nonzero mask. Any quad that would be out-of-bounds (only
    // possible for quad 8 when zal==224) is provably all-zero, so the mask
    // also guards addressing.
    unsigned qm = 0;
#pragma unroll
    for (int q = 0; q < 9; ++q) {
        if (wz[4*q] != 0.f || wz[4*q+1] != 0.f || wz[4*q+2] != 0.f || wz[4*q+3] != 0.f)
            qm |= (1u << q);
    }

#pragma unroll
    for (int r = 0; r < 4; ++r) {
        const int row = t + 256 * r;
        const int x = row >> 5;
        const int y = row & 31;
        const float f = swx[x] * swy[y];
        if (f == 0.0f) continue;

        float* base = vol + (((size_t)(sx + x) * VOLD + (sy + y)) * VOLD + zal);
#pragma unroll
        for (int q = 0; q < 9; ++q) {
            if ((qm >> q) & 1u) {
                const float a = f * wz[4*q + 0];
                const float b = f * wz[4*q + 1];
                const float c = f * wz[4*q + 2];
                const float d = f * wz[4*q + 3];
                asm volatile(
                    "red.global.add.v4.f32 [%0], {%1, %2, %3, %4};"
                    :: "l"(base + 4*q), "f"(a), "f"(b), "f"(c), "f"(d)
                    : "memory");
            }
        }
    }
}

// ---------------------------------------------------------------------------
extern "C" void kernel_launch(void* const* d_in, const int* in_sizes, int n_in,
                              void* d_out, int out_size) {
    const float* centers = (const float*)d_in[0];   // N*3
    const float* sigmas  = (const float*)d_in[1];   // N
    const float* intens  = (const float*)d_in[2];   // N
    float* vol = (float*)d_out;                     // 256^3

    const int n4 = (VOLD * VOLD * VOLD) / 4;
    zero_kernel<<<4096, 256>>>((float4*)vol, n4);
    splat_kernel<<<NGAUSS, 256>>>(centers, sigmas, intens, vol);
}

// round 2
// speedup vs baseline: 1.6433x; 1.6433x over previous
#include <cuda_runtime.h>
#include <math.h>

#define VOLD   256
#define NGAUSS 4000
#define TS     8                    // tile side
#define TPA    (VOLD / TS)          // 32 tiles per axis
#define NTILES (TPA * TPA * TPA)    // 32768
#define CAP    128                  // max gaussians per tile
#define BATCH  8                    // pairs staged per barrier

// ---------------------------------------------------------------------------
// Device-global scratch (allocation-free per harness rules)
// ---------------------------------------------------------------------------
__device__ float          g_wgt[NGAUSS * 3 * 32];   // per-axis weights (I folded into x)
__device__ int            g_start[NGAUSS * 3];      // window start per axis
__device__ int            g_cnt[NTILES];            // gaussians per tile
__device__ unsigned short g_bins[NTILES * CAP];     // gaussian ids per tile

// ---------------------------------------------------------------------------
// Kernel 1: zero the tile counters (128 KB)
// ---------------------------------------------------------------------------
__global__ void zero_cnt_kernel() {
    int i = blockIdx.x * blockDim.x + threadIdx.x;
    int4* p = (int4*)g_cnt;
    if (i < NTILES / 4) p[i] = make_int4(0, 0, 0, 0);
}

// ---------------------------------------------------------------------------
// Kernel 2: per-Gaussian weight vectors + tile binning. One block per Gaussian.
// ---------------------------------------------------------------------------
__global__ __launch_bounds__(128) void prep_kernel(
    const float* __restrict__ centers,
    const float* __restrict__ sigmas,
    const float* __restrict__ intens)
{
    const int g = blockIdx.x;
    const int t = threadIdx.x;

    __shared__ int s_tmin[3], s_tn[3];

    const float sig    = sigmas[g];
    const float inv2s2 = 0.5f / (sig * sig);
    const float I      = intens[g];
    const float cut    = 3.0f * sig * 255.0f;

    if (t < 96) {
        const int axis = t >> 5;
        const int o    = t & 31;

        const float cn = centers[3 * g + axis];
        const float cv = cn * 255.0f;

        const float minf = fmaxf(cv - cut, 0.0f);
        const float maxf = fminf(cv + cut, 255.0f);
        const int   mini = (int)floorf(minf);
        const int   maxi = min((int)floorf(maxf) + 1, VOLD);   // exclusive
        const int   start = min(mini, VOLD - 32);

        const int idx = start + o;
        float w = 0.0f;
        if (idx >= mini && idx < maxi) {
            const float d = (float)idx * (1.0f / 255.0f) - cn;
            w = expf(-d * d * inv2s2);
        }
        if (axis == 0) w *= I;
        g_wgt[(g * 3 + axis) * 32 + o] = w;

        if (o == 0) {
            g_start[g * 3 + axis] = start;
            const int tmin = mini >> 3;
            const int tmax = (maxi - 1) >> 3;
            s_tmin[axis] = tmin;
            s_tn[axis]   = tmax - tmin + 1;
        }
    }
    __syncthreads();

    const int nx = s_tn[0], ny = s_tn[1], nz = s_tn[2];
    const int total = nx * ny * nz;
    for (int i = t; i < total; i += 128) {
        const int iz = i % nz;
        const int iy = (i / nz) % ny;
        const int ix = i / (nz * ny);
        const int tile = ((s_tmin[0] + ix) * TPA + (s_tmin[1] + iy)) * TPA
                         + (s_tmin[2] + iz);
        const int pos = atomicAdd(&g_cnt[tile], 1);
        if (pos < CAP) g_bins[tile * CAP + pos] = (unsigned short)g;
    }
}

// ---------------------------------------------------------------------------
// Kernel 3: gather. One block per 8x8x8 tile; each thread owns a z-quad of
// 4 voxels; contributions summed in registers, written once as float4.
// ---------------------------------------------------------------------------
__global__ __launch_bounds__(128) void gather_kernel(float* __restrict__ vol) {
    const int tile = blockIdx.x;
    const int t    = threadIdx.x;

    const int tzi = tile & (TPA - 1);
    const int tyi = (tile >> 5) & (TPA - 1);
    const int txi = tile >> 10;
    const int ox = txi * TS, oy = tyi * TS, oz = tzi * TS;

    const int cnt = min(g_cnt[tile], CAP);

    // voxel mapping: v = 4t; x = v>>6, y = (v>>3)&7, z in [zb, zb+4)
    const int v  = 4 * t;
    const int x  = v >> 6;
    const int y  = (v >> 3) & 7;
    const int zb = v & 7;          // 0 or 4

    float a0 = 0.f, a1 = 0.f, a2 = 0.f, a3 = 0.f;

    __shared__ __align__(16) float s_w[BATCH][3][8];

    for (int base = 0; base < cnt; base += BATCH) {
        const int nb = min(BATCH, cnt - base);

        // stage per-axis weight slices for nb pairs (24 floats each)
        for (int i = t; i < nb * 24; i += 128) {
            const int p    = i / 24;
            const int r    = i - p * 24;
            const int axis = r >> 3;
            const int o    = r & 7;
            const int gid  = g_bins[tile * CAP + base + p];
            const int og   = (axis == 0 ? ox : (axis == 1 ? oy : oz)) + o;
            const int k    = og - g_start[gid * 3 + axis];
            s_w[p][axis][o] = ((unsigned)k < 32u)
                              ? g_wgt[(gid * 3 + axis) * 32 + k] : 0.f;
        }
        __syncthreads();

#pragma unroll
        for (int p = 0; p < BATCH; ++p) {
            if (p >= nb) break;
            const float f = s_w[p][0][x] * s_w[p][1][y];
            const float4 wz = *(const float4*)&s_w[p][2][zb];
            a0 = fmaf(f, wz.x, a0);
            a1 = fmaf(f, wz.y, a1);
            a2 = fmaf(f, wz.z, a2);
            a3 = fmaf(f, wz.w, a3);
        }
        __syncthreads();
    }

    float4 out = make_float4(a0, a1, a2, a3);
    const size_t off = ((size_t)(ox + x) * VOLD + (oy + y)) * VOLD + oz + zb;
    *(float4*)(vol + off) = out;
}

// ---------------------------------------------------------------------------
extern "C" void kernel_launch(void* const* d_in, const int* in_sizes, int n_in,
                              void* d_out, int out_size) {
    const float* centers = (const float*)d_in[0];
    const float* sigmas  = (const float*)d_in[1];
    const float* intens  = (const float*)d_in[2];
    float* vol = (float*)d_out;

    zero_cnt_kernel<<<(NTILES / 4 + 255) / 256, 256>>>();
    prep_kernel<<<NGAUSS, 128>>>(centers, sigmas, intens);
    gather_kernel<<<NTILES, 128>>>(vol);
}